// round 13
// baseline (speedup 1.0000x reference)
#include <cuda_runtime.h>
#include <cuda_fp16.h>
#include <cstdint>
#include <math.h>

#define HID    768
#define FFNDIM 3072
#define NE     8
#define TMAX   16384

// ---------------- scratch (device globals: allocation-free) ----------------
__device__ __half g_xh [TMAX * HID];            // fp16 X
__device__ __half g_w1h[NE * FFNDIM * HID];     // w1 transposed: [E][FFN][HID] fp16
__device__ __half g_w2h[NE * HID * FFNDIM];     // w2 transposed: [E][HID][FFN] fp16
__device__ __half g_Hh [2 * TMAX * FFNDIM];     // gelu(X@w1+b1) fp16
__device__ float  g_Y  [2 * TMAX * HID];        // H@w2+b2 per pair (fp32)
__device__ int    g_cnt[NE];
__device__ int    g_off[NE];
__device__ int    g_list[NE * TMAX];
__device__ int    g_pe  [2 * TMAX];
__device__ int    g_ps  [2 * TMAX];
__device__ float  g_pgate[2 * TMAX];
__device__ float  g_probsum[NE];
__device__ float  g_gatesum[NE];
__device__ int    g_done1[NE];                  // gemm1 per-expert CTA completion

// ---------------- helpers ----------------
__device__ __forceinline__ void cp16(uint32_t dst, const void* src) {
    asm volatile("cp.async.cg.shared.global [%0], [%1], 16;" :: "r"(dst), "l"(src));
}
__device__ __forceinline__ float fast_tanh(float y) {
    float t = __expf(2.0f * fminf(fabsf(y), 15.0f));
    float r = (t - 1.0f) / (t + 1.0f);
    return copysignf(r, y);
}
__device__ __forceinline__ float gelu_tanh(float x) {
    float x3 = x * x * x;
    return 0.5f * x * (1.0f + fast_tanh(0.7978845608028654f * (x + 0.044715f * x3)));
}

#define LDSM4(r0, r1, r2, r3, addr) \
    asm volatile("ldmatrix.sync.aligned.m8n8.x4.shared.b16 {%0,%1,%2,%3}, [%4];" \
                 : "=r"(r0), "=r"(r1), "=r"(r2), "=r"(r3) : "r"(addr))

#define MMA16816(acc, a, b) \
    asm volatile( \
        "mma.sync.aligned.m16n8k16.row.col.f32.f16.f16.f32 " \
        "{%0,%1,%2,%3}, {%4,%5,%6,%7}, {%8,%9}, {%0,%1,%2,%3};\n" \
        : "+f"((acc)[0]), "+f"((acc)[1]), "+f"((acc)[2]), "+f"((acc)[3]) \
        : "r"((a)[0]), "r"((a)[1]), "r"((a)[2]), "r"((a)[3]), \
          "r"((b)[0]), "r"((b)[1]))

// ---------------- init ----------------
__global__ void init_kernel() {
    int i = threadIdx.x;
    if (i < NE) {
        g_cnt[i] = 0; g_probsum[i] = 0.f; g_gatesum[i] = 0.f; g_done1[i] = 0;
    }
}

// ---------------- megaprep: w1^T + w2^T + x-convert + router in ONE launch --
__global__ void __launch_bounds__(256) megaprep_kernel(
    const float* __restrict__ x,  const float* __restrict__ w1,
    const float* __restrict__ w2, const float* __restrict__ rw,
    const float* __restrict__ rb,
    float* __restrict__ out_rw, float* __restrict__ out_mask,
    float* __restrict__ out_logits, int T)
{
    __shared__ float tile[32][33];
    __shared__ float srw[NE * HID];
    __shared__ float sprob[NE];
    __shared__ float sgate[NE];

    const int tx = threadIdx.x, ty = threadIdx.y;
    const int tid = ty * 32 + tx;
    const int z = blockIdx.z;

    if (z < 16) {
        const int e = z & 7;
        const float* s;
        __half* d;
        int c0, r0, srcC, dstR;
        if (z < NE) {       // w1: src [HID][FFN] -> dst [FFN][HID]
            s = w1 + (size_t)e * HID * FFNDIM;
            d = g_w1h + (size_t)e * HID * FFNDIM;
            c0 = blockIdx.x * 32; r0 = blockIdx.y * 32;
            srcC = FFNDIM; dstR = HID;
        } else {            // w2: src [FFN][HID] -> dst [HID][FFN]
            s = w2 + (size_t)e * FFNDIM * HID;
            d = g_w2h + (size_t)e * FFNDIM * HID;
            c0 = blockIdx.y * 32; r0 = blockIdx.x * 32;
            srcC = HID; dstR = FFNDIM;
        }
        #pragma unroll
        for (int i = 0; i < 32; i += 8)
            tile[ty + i][tx] = s[(size_t)(r0 + ty + i) * srcC + c0 + tx];
        __syncthreads();
        #pragma unroll
        for (int i = 0; i < 32; i += 8)
            d[(size_t)(c0 + ty + i) * dstR + r0 + tx] = __float2half_rn(tile[tx][ty + i]);
        return;
    }

    if (z == 16) {
        int bid = blockIdx.y * gridDim.x + blockIdx.x;
        int n = T * HID;
        int nb = gridDim.x * gridDim.y;
        for (int i = bid * 256 + tid; i < n; i += nb * 256)
            g_xh[i] = __float2half_rn(x[i]);
        return;
    }

    // z == 17: router
    for (int i = tid; i < NE * HID; i += 256) {
        int e = i / HID, c = i - e * HID;
        srw[i] = rw[c * NE + e];
    }
    if (tid < NE) { sprob[tid] = 0.f; sgate[tid] = 0.f; }
    __syncthreads();

    const int warp = ty, lane = tx;
    const int bid = blockIdx.y * gridDim.x + blockIdx.x;
    const int t = bid * 8 + warp;
    if (t < T) {
        float p[NE];
        #pragma unroll
        for (int e = 0; e < NE; e++) p[e] = 0.f;
        const float* xr = x + (size_t)t * HID;
        for (int c = lane; c < HID; c += 32) {
            float xv = xr[c];
            #pragma unroll
            for (int e = 0; e < NE; e++) p[e] += xv * srw[e * HID + c];
        }
        #pragma unroll
        for (int e = 0; e < NE; e++) {
            #pragma unroll
            for (int o = 16; o > 0; o >>= 1)
                p[e] += __shfl_xor_sync(0xffffffffu, p[e], o);
        }
        if (lane == 0) {
            float lg[NE];
            #pragma unroll
            for (int e = 0; e < NE; e++) lg[e] = p[e] + rb[e];
            float m = lg[0];
            #pragma unroll
            for (int e = 1; e < NE; e++) m = fmaxf(m, lg[e]);
            float s = 0.f, pr[NE];
            #pragma unroll
            for (int e = 0; e < NE; e++) { pr[e] = expf(lg[e] - m); s += pr[e]; }
            float inv = 1.f / s;
            #pragma unroll
            for (int e = 0; e < NE; e++) {
                pr[e] *= inv;
                out_logits[(size_t)t * NE + e] = lg[e];
                out_rw[(size_t)t * NE + e] = pr[e];
                atomicAdd(&sprob[e], pr[e]);
            }
            int i1 = 0; float v1 = lg[0];
            #pragma unroll
            for (int e = 1; e < NE; e++) if (lg[e] > v1) { v1 = lg[e]; i1 = e; }
            int i2 = -1; float v2 = -3.4e38f;
            #pragma unroll
            for (int e = 0; e < NE; e++)
                if (e != i1 && lg[e] > v2) { v2 = lg[e]; i2 = e; }
            float texp = expf(v2 - v1);
            float gden = 1.f / (1.f + texp);
            float gg1 = gden, gg2 = texp * gden;
            #pragma unroll
            for (int e = 0; e < NE; e++) {
                float mv = (e == i1) ? gg1 : ((e == i2) ? gg2 : 0.f);
                out_mask[(size_t)t * NE + e] = mv;
            }
            int pos1 = atomicAdd(&g_cnt[i1], 1);
            g_list[i1 * TMAX + pos1] = t;
            g_pe[2 * t] = i1; g_ps[2 * t] = pos1; g_pgate[2 * t] = gg1;
            int pos2 = atomicAdd(&g_cnt[i2], 1);
            g_list[i2 * TMAX + pos2] = t;
            g_pe[2 * t + 1] = i2; g_ps[2 * t + 1] = pos2; g_pgate[2 * t + 1] = gg2;
            atomicAdd(&sgate[i1], gg1);
            atomicAdd(&sgate[i2], gg2);
        }
    }
    __syncthreads();
    if (tid < NE) {
        atomicAdd(&g_probsum[tid], sprob[tid]);
        atomicAdd(&g_gatesum[tid], sgate[tid]);
    }
}

__global__ void offsets_kernel(float* __restrict__ out_aux, int T) {
    if (threadIdx.x == 0 && blockIdx.x == 0) {
        int acc = 0;
        float aux = 0.f;
        #pragma unroll
        for (int e = 0; e < NE; e++) {
            g_off[e] = acc;
            acc += g_cnt[e];
            aux += g_probsum[e] * g_gatesum[e];
        }
        out_aux[0] = aux * (float)NE / ((float)T * (float)T);
    }
}

// ---------------- fused gemm body (round-8 winner, unchanged math) ----------
#define BM      256
#define BN      128
#define BK      64
#define ROWH    72                    // padded row length in halves (144 B)
#define ROWB    144
#define TILEA_B (BM * ROWB)           // 36864 B
#define TILEB_B (BN * ROWB)           // 18432 B
#define STAGEB  (TILEA_B + TILEB_B)   // 55296 B
#define NSTAGE  4

// EPI=1: A = gathered g_xh rows, B = g_w1h, out = fp16(gelu(.+b1)) -> g_Hh
//        signals g_done1[e] on completion (including early-exit duds).
// EPI=2: waits g_done1[e]==p1cnt, A = g_Hh, B = g_w2h, out = .+b2 -> g_Y
template<int KDIM, int NDIM, int EPI>
__device__ __forceinline__ void gemm_body(int e, int rem, const float* __restrict__ bias,
                                          int p1cnt)
{
    const int nt   = NDIM / BN;
    const int n0   = (rem % nt) * BN;
    const int m0   = (rem / nt) * BM;
    const int cnt  = g_cnt[e];
    const int off  = g_off[e];

    if (m0 >= cnt) {
        if (EPI == 1 && threadIdx.x == 0) atomicAdd(&g_done1[e], 1);
        return;
    }
    if (EPI == 2) {
        if (threadIdx.x == 0) {
            while (atomicAdd(&g_done1[e], 0) < p1cnt) __nanosleep(200);
        }
        __syncthreads();
    }

    extern __shared__ __half smem[];
    const uint32_t SB = (uint32_t)__cvta_generic_to_shared(smem);

    const int tid  = threadIdx.x;
    const int lane = tid & 31;
    const int wid  = tid >> 5;
    const int wm   = wid >> 2;          // 0..3
    const int wn   = wid & 3;           // 0..3
    const int gid  = lane >> 2;         // 0..7
    const int tig  = lane & 3;          // 0..3

    // ---- cp.async plumbing: 4 A rows + 2 B rows per thread ----
    const int chunk = tid & 7;
    const int row4  = tid >> 3;         // 0..63
    const __half* asrc[4];
    const __half* bsrc[2];
    uint32_t adst[4], bdst[2];
    const __half* wT = (EPI == 1 ? g_w1h : g_w2h) + (size_t)e * KDIM * NDIM;
    #pragma unroll
    for (int i = 0; i < 4; i++) {
        int row = row4 + 64 * i;        // 0..255
        int slot = m0 + row;
        if (slot > cnt - 1) slot = cnt - 1;
        if (EPI == 1) {
            int tok = g_list[e * TMAX + slot];
            asrc[i] = g_xh + (size_t)tok * KDIM + chunk * 8;
        } else {
            asrc[i] = g_Hh + (size_t)(off + slot) * KDIM + chunk * 8;
        }
        adst[i] = SB + (uint32_t)(row * ROWB + chunk * 16);
    }
    #pragma unroll
    for (int i = 0; i < 2; i++) {
        int row = row4 + 64 * i;        // 0..127
        bsrc[i] = wT + (size_t)(n0 + row) * KDIM + chunk * 8;
        bdst[i] = SB + TILEA_B + (uint32_t)(row * ROWB + chunk * 16);
    }

    auto load_stage = [&](int s, int k0) {
        uint32_t so = (uint32_t)s * STAGEB;
        #pragma unroll
        for (int i = 0; i < 4; i++) cp16(adst[i] + so, asrc[i] + k0);
        #pragma unroll
        for (int i = 0; i < 2; i++) cp16(bdst[i] + so, bsrc[i] + k0);
    };

    float acc[4][4][4];
    #pragma unroll
    for (int mi = 0; mi < 4; mi++)
        #pragma unroll
        for (int ni = 0; ni < 4; ni++)
            #pragma unroll
            for (int r = 0; r < 4; r++) acc[mi][ni][r] = 0.f;

    constexpr int NKT = KDIM / BK;
    load_stage(0, 0);
    asm volatile("cp.async.commit_group;" ::: "memory");
    load_stage(1, BK);
    asm volatile("cp.async.commit_group;" ::: "memory");

    const int mbase = wm * 64;
    const int nbase = wn * 32;

    const int lgrp = lane >> 3, lr = lane & 7;
    const uint32_t a_lane = (uint32_t)((((lgrp & 1) * 8 + lr) * ROWH + (lgrp >> 1) * 8) * 2);
    const uint32_t b_lane = (uint32_t)((((lgrp >> 1) * 8 + lr) * ROWH + (lgrp & 1) * 8) * 2);

    for (int kt = 0; kt < NKT; kt++) {
        if (kt + 2 < NKT) load_stage((kt + 2) & 3, (kt + 2) * BK);
        asm volatile("cp.async.commit_group;" ::: "memory");
        asm volatile("cp.async.wait_group 2;" ::: "memory");
        __syncthreads();

        const uint32_t stage = SB + (uint32_t)(kt & 3) * STAGEB;
        const uint32_t asb = stage + (uint32_t)(mbase * ROWB) + a_lane;
        const uint32_t bsb = stage + TILEA_B + (uint32_t)(nbase * ROWB) + b_lane;
        #pragma unroll
        for (int kk = 0; kk < BK; kk += 16) {
            uint32_t a[4][4], b[4][2];
            #pragma unroll
            for (int mi = 0; mi < 4; mi++)
                LDSM4(a[mi][0], a[mi][1], a[mi][2], a[mi][3],
                      asb + (uint32_t)(mi * 16 * ROWB + kk * 2));
            #pragma unroll
            for (int p = 0; p < 2; p++)
                LDSM4(b[2 * p][0], b[2 * p][1], b[2 * p + 1][0], b[2 * p + 1][1],
                      bsb + (uint32_t)(p * 16 * ROWB + kk * 2));
            #pragma unroll
            for (int mi = 0; mi < 4; mi++)
                #pragma unroll
                for (int ni = 0; ni < 4; ni++)
                    MMA16816(acc[mi][ni], a[mi], b[ni]);
        }
    }

    // ---- epilogue ----
    #pragma unroll
    for (int ni = 0; ni < 4; ni++) {
        int cc = n0 + wn * 32 + ni * 8 + 2 * tig;
        float bv0 = bias[e * NDIM + cc];
        float bv1 = bias[e * NDIM + cc + 1];
        #pragma unroll
        for (int mi = 0; mi < 4; mi++) {
            int r = m0 + wm * 64 + mi * 16 + gid;
            #pragma unroll
            for (int h = 0; h < 2; h++) {
                int rr = r + h * 8;
                if (rr < cnt) {
                    float v0 = acc[mi][ni][2 * h]     + bv0;
                    float v1 = acc[mi][ni][2 * h + 1] + bv1;
                    if (EPI == 1) {
                        __half2 hv = __floats2half2_rn(gelu_tanh(v0), gelu_tanh(v1));
                        *reinterpret_cast<__half2*>(
                            &g_Hh[(size_t)(off + rr) * NDIM + cc]) = hv;
                    } else {
                        float2 st; st.x = v0; st.y = v1;
                        *reinterpret_cast<float2*>(
                            &g_Y[(size_t)(off + rr) * NDIM + cc]) = st;
                    }
                }
            }
        }
    }

    if (EPI == 1) {
        __syncthreads();
        __threadfence();
        if (threadIdx.x == 0) atomicAdd(&g_done1[e], 1);
    }
}

// Fused launch: 1D grid of 8*(p1+p2) CTAs.
// Segment order interleaves gemm2-e AFTER gemm1-e (dependency always already
// dispatched under FIFO CTA dispatch -> no deadlock; spinners are bounded):
//   g1e0, g1e1, g2e0, g1e2, g2e1, g1e3, g2e2, g1e4, g2e3,
//   g1e5, g2e4, g1e6, g2e5, g1e7, g2e6, g2e7
__global__ void __launch_bounds__(512, 1) fusedgemm_kernel(
    const float* __restrict__ b1, const float* __restrict__ b2, int mt)
{
    const int p1 = (FFNDIM / BN) * mt;     // gemm1 CTAs per expert
    const int p2 = (HID / BN) * mt;        // gemm2 CTAs per expert
    const unsigned char phs[16] = {1,1,2,1,2,1,2,1,2,1,2,1,2,1,2,2};
    const unsigned char exs[16] = {0,1,0,2,1,3,2,4,3,5,4,6,5,7,6,7};

    int b = (int)blockIdx.x;
    int phase = 0, e = 0, rem = 0;
    #pragma unroll
    for (int s = 0; s < 16; s++) {
        int sz = (phs[s] == 1) ? p1 : p2;
        if (phase == 0) {
            if (b < sz) { phase = phs[s]; e = exs[s]; rem = b; }
            else        { b -= sz; }
        }
    }
    if (phase == 1) gemm_body<HID, FFNDIM, 1>(e, rem, b1, p1);
    else            gemm_body<FFNDIM, HID, 2>(e, rem, b2, p1);
}

__global__ void combine_kernel(float* __restrict__ out, int T) {
    int total = T * (HID / 4);
    for (int i = blockIdx.x * blockDim.x + threadIdx.x; i < total;
         i += gridDim.x * blockDim.x) {
        int t = i / (HID / 4);
        int c = i - t * (HID / 4);
        int p0 = g_off[g_pe[2 * t]]     + g_ps[2 * t];
        int p1 = g_off[g_pe[2 * t + 1]] + g_ps[2 * t + 1];
        float gg0 = g_pgate[2 * t], gg1 = g_pgate[2 * t + 1];
        const float4 a = *reinterpret_cast<const float4*>(&g_Y[(size_t)p0 * HID + 4 * c]);
        const float4 b = *reinterpret_cast<const float4*>(&g_Y[(size_t)p1 * HID + 4 * c]);
        float4 o;
        o.x = gg0 * a.x + gg1 * b.x;
        o.y = gg0 * a.y + gg1 * b.y;
        o.z = gg0 * a.z + gg1 * b.z;
        o.w = gg0 * a.w + gg1 * b.w;
        reinterpret_cast<float4*>(out)[i] = o;
    }
}

// ---------------- launch ----------------
extern "C" void kernel_launch(void* const* d_in, const int* in_sizes, int n_in,
                              void* d_out, int out_size)
{
    const float* x  = (const float*)d_in[0];
    const float* rw = (const float*)d_in[1];
    const float* rb = (const float*)d_in[2];
    const float* w1 = (const float*)d_in[3];
    const float* b1 = (const float*)d_in[4];
    const float* w2 = (const float*)d_in[5];
    const float* b2 = (const float*)d_in[6];
    int T = in_sizes[0] / HID;
    if (T > TMAX) T = TMAX;

    float* out        = (float*)d_out;
    float* out_comb   = out;
    float* out_rw     = out + (size_t)T * HID;
    float* out_mask   = out_rw + (size_t)T * NE;
    float* out_aux    = out_mask + (size_t)T * NE;
    float* out_logits = out_aux + 1;

    const int smem = NSTAGE * STAGEB;   // 221184 B
    cudaFuncSetAttribute(fusedgemm_kernel,
                         cudaFuncAttributeMaxDynamicSharedMemorySize, smem);

    const int mt = (T + BM - 1) / BM;
    const int p1 = (FFNDIM / BN) * mt;
    const int p2 = (HID / BN) * mt;
    const int total_ctas = NE * (p1 + p2);

    // order keeps fusedgemm at launch slot #4 for the fixed-slot ncu capture
    init_kernel<<<1, 32>>>();
    megaprep_kernel<<<dim3(96, 24, 18), dim3(32, 8)>>>(
        x, w1, w2, rw, rb, out_rw, out_mask, out_logits, T);
    offsets_kernel<<<1, 32>>>(out_aux, T);

    fusedgemm_kernel<<<total_ctas, 512, smem>>>(b1, b2, mt);

    combine_kernel<<<4096, 256>>>(out_comb, T);
}

// round 14
// speedup vs baseline: 1.0476x; 1.0476x over previous
#include <cuda_runtime.h>
#include <cuda_fp16.h>
#include <cstdint>
#include <math.h>

#define HID    768
#define FFNDIM 3072
#define NE     8
#define TMAX   16384

// ---------------- scratch (device globals: allocation-free) ----------------
__device__ __half g_xh [TMAX * HID];            // fp16 X
__device__ __half g_w1h[NE * FFNDIM * HID];     // w1 transposed: [E][FFN][HID] fp16
__device__ __half g_w2h[NE * HID * FFNDIM];     // w2 transposed: [E][HID][FFN] fp16
__device__ __half g_Hh [2 * TMAX * FFNDIM];     // gelu(X@w1+b1) fp16
__device__ float  g_Y  [2 * TMAX * HID];        // H@w2+b2 per pair (fp32)
__device__ int    g_cnt[NE];
__device__ int    g_off[NE];
__device__ int    g_list[NE * TMAX];
__device__ int    g_pe  [2 * TMAX];
__device__ int    g_ps  [2 * TMAX];
__device__ float  g_pgate[2 * TMAX];
__device__ float  g_probsum[NE];
__device__ float  g_gatesum[NE];

// ---------------- helpers ----------------
__device__ __forceinline__ void cp16(uint32_t dst, const void* src) {
    asm volatile("cp.async.cg.shared.global [%0], [%1], 16;" :: "r"(dst), "l"(src));
}
__device__ __forceinline__ float fast_tanh(float y) {
    float t = __expf(2.0f * fminf(fabsf(y), 15.0f));
    float r = (t - 1.0f) / (t + 1.0f);
    return copysignf(r, y);
}
__device__ __forceinline__ float gelu_tanh(float x) {
    float x3 = x * x * x;
    return 0.5f * x * (1.0f + fast_tanh(0.7978845608028654f * (x + 0.044715f * x3)));
}

#define LDSM4(r0, r1, r2, r3, addr) \
    asm volatile("ldmatrix.sync.aligned.m8n8.x4.shared.b16 {%0,%1,%2,%3}, [%4];" \
                 : "=r"(r0), "=r"(r1), "=r"(r2), "=r"(r3) : "r"(addr))

#define MMA16816(acc, a, b) \
    asm volatile( \
        "mma.sync.aligned.m16n8k16.row.col.f32.f16.f16.f32 " \
        "{%0,%1,%2,%3}, {%4,%5,%6,%7}, {%8,%9}, {%0,%1,%2,%3};\n" \
        : "+f"((acc)[0]), "+f"((acc)[1]), "+f"((acc)[2]), "+f"((acc)[3]) \
        : "r"((a)[0]), "r"((a)[1]), "r"((a)[2]), "r"((a)[3]), \
          "r"((b)[0]), "r"((b)[1]))

// ---------------- prep1: w1 transpose + init (fused) ----------------
// grid (96, 24, 8), block (32, 8). Block (0,0,0) also zeroes the counters
// (ordered before the router's atomics by the kernel boundary).
__global__ void prep1_kernel(const float* __restrict__ w1) {
    __shared__ float tile[32][33];
    const int tx = threadIdx.x, ty = threadIdx.y;
    const int tid = ty * 32 + tx;
    if (blockIdx.x == 0 && blockIdx.y == 0 && blockIdx.z == 0 && tid < NE) {
        g_cnt[tid] = 0; g_probsum[tid] = 0.f; g_gatesum[tid] = 0.f;
    }
    const int e = blockIdx.z;
    const float* s = w1 + (size_t)e * HID * FFNDIM;
    __half* d = g_w1h + (size_t)e * HID * FFNDIM;
    int c0 = blockIdx.x * 32, r0 = blockIdx.y * 32;   // c in FFN, r in HID
    #pragma unroll
    for (int i = 0; i < 32; i += 8)
        tile[ty + i][tx] = s[(size_t)(r0 + ty + i) * FFNDIM + c0 + tx];
    __syncthreads();
    #pragma unroll
    for (int i = 0; i < 32; i += 8)
        d[(size_t)(c0 + ty + i) * HID + r0 + tx] = __float2half_rn(tile[tx][ty + i]);
}

// one warp per token; ALSO writes the fp16 conversion of x (fused convert)
__global__ void __launch_bounds__(256) router_kernel(
    const float* __restrict__ x, const float* __restrict__ rw,
    const float* __restrict__ rb,
    float* __restrict__ out_rw, float* __restrict__ out_mask,
    float* __restrict__ out_logits, int T)
{
    __shared__ float srw[NE * HID];
    __shared__ float sprob[NE];
    __shared__ float sgate[NE];
    int tid = threadIdx.x;
    for (int i = tid; i < NE * HID; i += blockDim.x) {
        int e = i / HID, c = i - e * HID;
        srw[i] = rw[c * NE + e];
    }
    if (tid < NE) { sprob[tid] = 0.f; sgate[tid] = 0.f; }
    __syncthreads();

    int warp = tid >> 5, lane = tid & 31;
    int t = blockIdx.x * 8 + warp;
    if (t < T) {
        float p[NE];
        #pragma unroll
        for (int e = 0; e < NE; e++) p[e] = 0.f;
        const float* xr = x + (size_t)t * HID;
        __half* xhr = g_xh + (size_t)t * HID;
        for (int c = lane; c < HID; c += 32) {
            float xv = xr[c];
            xhr[c] = __float2half_rn(xv);        // fused fp16 convert
            #pragma unroll
            for (int e = 0; e < NE; e++) p[e] += xv * srw[e * HID + c];
        }
        #pragma unroll
        for (int e = 0; e < NE; e++) {
            #pragma unroll
            for (int o = 16; o > 0; o >>= 1)
                p[e] += __shfl_xor_sync(0xffffffffu, p[e], o);
        }
        if (lane == 0) {
            float lg[NE];
            #pragma unroll
            for (int e = 0; e < NE; e++) lg[e] = p[e] + rb[e];
            float m = lg[0];
            #pragma unroll
            for (int e = 1; e < NE; e++) m = fmaxf(m, lg[e]);
            float s = 0.f, pr[NE];
            #pragma unroll
            for (int e = 0; e < NE; e++) { pr[e] = expf(lg[e] - m); s += pr[e]; }
            float inv = 1.f / s;
            #pragma unroll
            for (int e = 0; e < NE; e++) {
                pr[e] *= inv;
                out_logits[(size_t)t * NE + e] = lg[e];
                out_rw[(size_t)t * NE + e] = pr[e];
                atomicAdd(&sprob[e], pr[e]);
            }
            int i1 = 0; float v1 = lg[0];
            #pragma unroll
            for (int e = 1; e < NE; e++) if (lg[e] > v1) { v1 = lg[e]; i1 = e; }
            int i2 = -1; float v2 = -3.4e38f;
            #pragma unroll
            for (int e = 0; e < NE; e++)
                if (e != i1 && lg[e] > v2) { v2 = lg[e]; i2 = e; }
            float texp = expf(v2 - v1);
            float gden = 1.f / (1.f + texp);
            float gg1 = gden, gg2 = texp * gden;
            #pragma unroll
            for (int e = 0; e < NE; e++) {
                float mv = (e == i1) ? gg1 : ((e == i2) ? gg2 : 0.f);
                out_mask[(size_t)t * NE + e] = mv;
            }
            int pos1 = atomicAdd(&g_cnt[i1], 1);
            g_list[i1 * TMAX + pos1] = t;
            g_pe[2 * t] = i1; g_ps[2 * t] = pos1; g_pgate[2 * t] = gg1;
            int pos2 = atomicAdd(&g_cnt[i2], 1);
            g_list[i2 * TMAX + pos2] = t;
            g_pe[2 * t + 1] = i2; g_ps[2 * t + 1] = pos2; g_pgate[2 * t + 1] = gg2;
            atomicAdd(&sgate[i1], gg1);
            atomicAdd(&sgate[i2], gg2);
        }
    }
    __syncthreads();
    if (tid < NE) {
        atomicAdd(&g_probsum[tid], sprob[tid]);
        atomicAdd(&g_gatesum[tid], sgate[tid]);
    }
}

__global__ void offsets_kernel(float* __restrict__ out_aux, int T) {
    if (threadIdx.x == 0 && blockIdx.x == 0) {
        int acc = 0;
        float aux = 0.f;
        #pragma unroll
        for (int e = 0; e < NE; e++) {
            g_off[e] = acc;
            acc += g_cnt[e];
            aux += g_probsum[e] * g_gatesum[e];
        }
        out_aux[0] = aux * (float)NE / ((float)T * (float)T);
    }
}

// ---------------- fp16 mma.sync grouped GEMM (round-8 winner) ----------------
// CTA tile 256(M) x 128(N) x 64(K), 512 threads = 16 warps (4x4), warp tile 64x32.
// 4-stage cp.async ring, prefetch dist 2, single sync per k-tile, ldmatrix.x4.
// gemm1 additionally carries grid z==NE: a w2-transpose slice (dispatched last,
// fills gemm1's draining tail; ready before gemm2 by stream order).
#define BM      256
#define BN      128
#define BK      64
#define ROWH    72                    // padded row length in halves (144 B)
#define ROWB    144
#define TILEA_B (BM * ROWB)           // 36864 B
#define TILEB_B (BN * ROWB)           // 18432 B
#define STAGEB  (TILEA_B + TILEB_B)   // 55296 B
#define NSTAGE  4

template<int KDIM, int NDIM, int EPI>
__global__ void __launch_bounds__(512, 1) gemmh_kernel(const float* __restrict__ bias,
                                                       const float* __restrict__ w2src)
{
    extern __shared__ __half smem[];

    if (EPI == 1 && blockIdx.z == NE) {
        // ---- w2 transpose slice: [E][FFN][HID] -> g_w2h [E][HID][FFN] ----
        float (*tile2)[32][33] = reinterpret_cast<float (*)[32][33]>(smem);
        const int tid  = threadIdx.x;
        const int sub  = tid >> 8;            // 0..1
        const int t8   = tid & 255;
        const int tx   = t8 & 31, ty = t8 >> 5;
        const int slot = ((int)blockIdx.y * 24 + (int)blockIdx.x) * 2 + sub; // 0..3071
        #pragma unroll
        for (int k = 0; k < 6; k++) {
            int tileid = slot + 3072 * k;     // 0..18431
            int e  = tileid / 2304;
            int rm = tileid - e * 2304;
            int fb = rm / 24;                 // FFN block 0..95
            int hb = rm - fb * 24;            // HID block 0..23
            const float* s = w2src + (size_t)e * FFNDIM * HID;
            __half* d = g_w2h + (size_t)e * FFNDIM * HID;
            int r0 = fb * 32, c0 = hb * 32;
            #pragma unroll
            for (int i = 0; i < 32; i += 8)
                tile2[sub][ty + i][tx] = s[(size_t)(r0 + ty + i) * HID + c0 + tx];
            __syncthreads();
            #pragma unroll
            for (int i = 0; i < 32; i += 8)
                d[(size_t)(c0 + ty + i) * FFNDIM + r0 + tx] =
                    __float2half_rn(tile2[sub][tx][ty + i]);
            __syncthreads();
        }
        return;
    }

    const int e   = blockIdx.z;
    const int cnt = g_cnt[e];
    const int m0  = blockIdx.y * BM;
    if (m0 >= cnt) return;
    const int n0  = blockIdx.x * BN;
    const int off = g_off[e];

    const uint32_t SB = (uint32_t)__cvta_generic_to_shared(smem);

    const int tid  = threadIdx.x;
    const int lane = tid & 31;
    const int wid  = tid >> 5;
    const int wm   = wid >> 2;          // 0..3
    const int wn   = wid & 3;           // 0..3
    const int gid  = lane >> 2;         // 0..7
    const int tig  = lane & 3;          // 0..3

    // ---- cp.async plumbing: 4 A rows + 2 B rows per thread ----
    const int chunk = tid & 7;          // 0..7  (16B = 8 halves)
    const int row4  = tid >> 3;         // 0..63
    const __half* asrc[4];
    const __half* bsrc[2];
    uint32_t adst[4], bdst[2];
    const __half* wT = (EPI == 1 ? g_w1h : g_w2h) + (size_t)e * KDIM * NDIM;
    #pragma unroll
    for (int i = 0; i < 4; i++) {
        int row = row4 + 64 * i;        // 0..255
        int slot = m0 + row;
        if (slot > cnt - 1) slot = cnt - 1;
        if (EPI == 1) {
            int tok = g_list[e * TMAX + slot];
            asrc[i] = g_xh + (size_t)tok * KDIM + chunk * 8;
        } else {
            asrc[i] = g_Hh + (size_t)(off + slot) * KDIM + chunk * 8;
        }
        adst[i] = SB + (uint32_t)(row * ROWB + chunk * 16);
    }
    #pragma unroll
    for (int i = 0; i < 2; i++) {
        int row = row4 + 64 * i;        // 0..127
        bsrc[i] = wT + (size_t)(n0 + row) * KDIM + chunk * 8;
        bdst[i] = SB + TILEA_B + (uint32_t)(row * ROWB + chunk * 16);
    }

    auto load_stage = [&](int s, int k0) {
        uint32_t so = (uint32_t)s * STAGEB;
        #pragma unroll
        for (int i = 0; i < 4; i++) cp16(adst[i] + so, asrc[i] + k0);
        #pragma unroll
        for (int i = 0; i < 2; i++) cp16(bdst[i] + so, bsrc[i] + k0);
    };

    float acc[4][4][4];
    #pragma unroll
    for (int mi = 0; mi < 4; mi++)
        #pragma unroll
        for (int ni = 0; ni < 4; ni++)
            #pragma unroll
            for (int r = 0; r < 4; r++) acc[mi][ni][r] = 0.f;

    constexpr int NKT = KDIM / BK;
    load_stage(0, 0);
    asm volatile("cp.async.commit_group;" ::: "memory");
    load_stage(1, BK);
    asm volatile("cp.async.commit_group;" ::: "memory");

    const int mbase = wm * 64;
    const int nbase = wn * 32;

    // ---- per-lane ldmatrix byte offsets (round-8 verified maps) ----
    const int lgrp = lane >> 3, lr = lane & 7;
    const uint32_t a_lane = (uint32_t)((((lgrp & 1) * 8 + lr) * ROWH + (lgrp >> 1) * 8) * 2);
    const uint32_t b_lane = (uint32_t)((((lgrp >> 1) * 8 + lr) * ROWH + (lgrp & 1) * 8) * 2);

    for (int kt = 0; kt < NKT; kt++) {
        if (kt + 2 < NKT) load_stage((kt + 2) & 3, (kt + 2) * BK);
        asm volatile("cp.async.commit_group;" ::: "memory");
        asm volatile("cp.async.wait_group 2;" ::: "memory");
        __syncthreads();

        const uint32_t stage = SB + (uint32_t)(kt & 3) * STAGEB;
        const uint32_t asb = stage + (uint32_t)(mbase * ROWB) + a_lane;
        const uint32_t bsb = stage + TILEA_B + (uint32_t)(nbase * ROWB) + b_lane;
        #pragma unroll
        for (int kk = 0; kk < BK; kk += 16) {
            uint32_t a[4][4], b[4][2];
            #pragma unroll
            for (int mi = 0; mi < 4; mi++)
                LDSM4(a[mi][0], a[mi][1], a[mi][2], a[mi][3],
                      asb + (uint32_t)(mi * 16 * ROWB + kk * 2));
            #pragma unroll
            for (int p = 0; p < 2; p++)
                LDSM4(b[2 * p][0], b[2 * p][1], b[2 * p + 1][0], b[2 * p + 1][1],
                      bsb + (uint32_t)(p * 16 * ROWB + kk * 2));
            #pragma unroll
            for (int mi = 0; mi < 4; mi++)
                #pragma unroll
                for (int ni = 0; ni < 4; ni++)
                    MMA16816(acc[mi][ni], a[mi], b[ni]);
        }
    }

    // ---- epilogue ----
    #pragma unroll
    for (int ni = 0; ni < 4; ni++) {
        int cc = n0 + wn * 32 + ni * 8 + 2 * tig;
        float bv0 = bias[e * NDIM + cc];
        float bv1 = bias[e * NDIM + cc + 1];
        #pragma unroll
        for (int mi = 0; mi < 4; mi++) {
            int r = m0 + wm * 64 + mi * 16 + gid;
            #pragma unroll
            for (int h = 0; h < 2; h++) {
                int rr = r + h * 8;
                if (rr < cnt) {
                    float v0 = acc[mi][ni][2 * h]     + bv0;
                    float v1 = acc[mi][ni][2 * h + 1] + bv1;
                    if (EPI == 1) {
                        __half2 hv = __floats2half2_rn(gelu_tanh(v0), gelu_tanh(v1));
                        *reinterpret_cast<__half2*>(
                            &g_Hh[(size_t)(off + rr) * NDIM + cc]) = hv;
                    } else {
                        float2 st; st.x = v0; st.y = v1;
                        *reinterpret_cast<float2*>(
                            &g_Y[(size_t)(off + rr) * NDIM + cc]) = st;
                    }
                }
            }
        }
    }
}

__global__ void combine_kernel(float* __restrict__ out, int T) {
    int total = T * (HID / 4);
    for (int i = blockIdx.x * blockDim.x + threadIdx.x; i < total;
         i += gridDim.x * blockDim.x) {
        int t = i / (HID / 4);
        int c = i - t * (HID / 4);
        int p0 = g_off[g_pe[2 * t]]     + g_ps[2 * t];
        int p1 = g_off[g_pe[2 * t + 1]] + g_ps[2 * t + 1];
        float gg0 = g_pgate[2 * t], gg1 = g_pgate[2 * t + 1];
        const float4 a = *reinterpret_cast<const float4*>(&g_Y[(size_t)p0 * HID + 4 * c]);
        const float4 b = *reinterpret_cast<const float4*>(&g_Y[(size_t)p1 * HID + 4 * c]);
        float4 o;
        o.x = gg0 * a.x + gg1 * b.x;
        o.y = gg0 * a.y + gg1 * b.y;
        o.z = gg0 * a.z + gg1 * b.z;
        o.w = gg0 * a.w + gg1 * b.w;
        reinterpret_cast<float4*>(out)[i] = o;
    }
}

// ---------------- launch ----------------
extern "C" void kernel_launch(void* const* d_in, const int* in_sizes, int n_in,
                              void* d_out, int out_size)
{
    const float* x  = (const float*)d_in[0];
    const float* rw = (const float*)d_in[1];
    const float* rb = (const float*)d_in[2];
    const float* w1 = (const float*)d_in[3];
    const float* b1 = (const float*)d_in[4];
    const float* w2 = (const float*)d_in[5];
    const float* b2 = (const float*)d_in[6];
    int T = in_sizes[0] / HID;
    if (T > TMAX) T = TMAX;

    float* out        = (float*)d_out;
    float* out_comb   = out;
    float* out_rw     = out + (size_t)T * HID;
    float* out_mask   = out_rw + (size_t)T * NE;
    float* out_aux    = out_mask + (size_t)T * NE;
    float* out_logits = out_aux + 1;

    const int smem = NSTAGE * STAGEB;   // 221184 B
    cudaFuncSetAttribute(gemmh_kernel<HID, FFNDIM, 1>,
                         cudaFuncAttributeMaxDynamicSharedMemorySize, smem);
    cudaFuncSetAttribute(gemmh_kernel<FFNDIM, HID, 2>,
                         cudaFuncAttributeMaxDynamicSharedMemorySize, smem);

    // launch order puts gemm1 at slot #4 for the fixed-slot ncu capture
    prep1_kernel<<<dim3(96, 24, 8), dim3(32, 8)>>>(w1);
    router_kernel<<<(T + 7) / 8, 256>>>(x, rw, rb, out_rw, out_mask, out_logits, T);
    offsets_kernel<<<1, 32>>>(out_aux, T);

    int mt = (T + BM - 1) / BM;
    gemmh_kernel<HID, FFNDIM, 1><<<dim3(FFNDIM / BN, mt, NE + 1), 512, smem>>>(b1, w2);
    gemmh_kernel<FFNDIM, HID, 2><<<dim3(HID / BN, mt, NE), 512, smem>>>(b2, nullptr);

    combine_kernel<<<4096, 256>>>(out_comb, T);
}

// round 15
// speedup vs baseline: 1.0491x; 1.0015x over previous
#include <cuda_runtime.h>
#include <cuda_fp16.h>
#include <cstdint>
#include <math.h>

#define HID    768
#define FFNDIM 3072
#define NE     8
#define TMAX   16384

// ---------------- scratch (device globals: allocation-free) ----------------
__device__ __half g_xh [TMAX * HID];            // fp16 X
__device__ __half g_w1h[NE * FFNDIM * HID];     // w1 transposed: [E][FFN][HID] fp16
__device__ __half g_w2h[NE * HID * FFNDIM];     // w2 transposed: [E][HID][FFN] fp16
__device__ __half g_Hh [2 * TMAX * FFNDIM];     // gelu(X@w1+b1) fp16
__device__ float  g_Y  [2 * TMAX * HID];        // H@w2+b2 per pair (fp32)
__device__ int    g_cnt[NE];
__device__ int    g_off[NE];
__device__ int    g_list[NE * TMAX];
__device__ int    g_pe  [2 * TMAX];
__device__ int    g_ps  [2 * TMAX];
__device__ float  g_pgate[2 * TMAX];
__device__ float  g_probsum[NE];
__device__ float  g_gatesum[NE];

// ---------------- helpers ----------------
__device__ __forceinline__ void cp16(uint32_t dst, const void* src) {
    asm volatile("cp.async.cg.shared.global [%0], [%1], 16;" :: "r"(dst), "l"(src));
}
__device__ __forceinline__ float fast_tanh(float y) {
    float t = __expf(2.0f * fminf(fabsf(y), 15.0f));
    float r = (t - 1.0f) / (t + 1.0f);
    return copysignf(r, y);
}
__device__ __forceinline__ float gelu_tanh(float x) {
    float x3 = x * x * x;
    return 0.5f * x * (1.0f + fast_tanh(0.7978845608028654f * (x + 0.044715f * x3)));
}

#define LDSM4(r0, r1, r2, r3, addr) \
    asm volatile("ldmatrix.sync.aligned.m8n8.x4.shared.b16 {%0,%1,%2,%3}, [%4];" \
                 : "=r"(r0), "=r"(r1), "=r"(r2), "=r"(r3) : "r"(addr))

#define MMA16816(acc, a, b) \
    asm volatile( \
        "mma.sync.aligned.m16n8k16.row.col.f32.f16.f16.f32 " \
        "{%0,%1,%2,%3}, {%4,%5,%6,%7}, {%8,%9}, {%0,%1,%2,%3};\n" \
        : "+f"((acc)[0]), "+f"((acc)[1]), "+f"((acc)[2]), "+f"((acc)[3]) \
        : "r"((a)[0]), "r"((a)[1]), "r"((a)[2]), "r"((a)[3]), \
          "r"((b)[0]), "r"((b)[1]))

// ---------------- init (orders before the front kernel's router atomics) ----
__global__ void init_kernel() {
    int i = threadIdx.x;
    if (i < NE) { g_cnt[i] = 0; g_probsum[i] = 0.f; g_gatesum[i] = 0.f; }
}

// ---------------- front: router (z=0, dispatched FIRST) + both transposes ---
// grid (96, 24, 17), block (32, 8).
//   z == 0      : router, one warp per token (bid*8 + warp), fused x->fp16
//   z in [1,9)  : transpose w1 expert z-1  (c0 = bx*32 in FFN, r0 = by*32 in HID)
//   z in [9,17) : transpose w2 expert z-9  (r0 = bx*32 in FFN, c0 = by*32 in HID)
// Router blocks dispatch first and hold the SMs; DRAM-bound transpose blocks
// backfill underneath/behind them.
__global__ void __launch_bounds__(256) front_kernel(
    const float* __restrict__ x,  const float* __restrict__ w1,
    const float* __restrict__ w2, const float* __restrict__ rw,
    const float* __restrict__ rb,
    float* __restrict__ out_rw, float* __restrict__ out_mask,
    float* __restrict__ out_logits, int T)
{
    __shared__ float tile[32][33];
    __shared__ float srw[NE * HID];
    __shared__ float sprob[NE];
    __shared__ float sgate[NE];

    const int tx = threadIdx.x, ty = threadIdx.y;
    const int tid = ty * 32 + tx;
    const int z = blockIdx.z;

    if (z > 0) {
        // ---- weight transposes ----
        const int zz = z - 1;
        const int e = zz & 7;
        const float* s;
        __half* d;
        int c0, r0, srcC, dstR;
        if (zz < NE) {      // w1: src [HID][FFN] -> dst [FFN][HID]
            s = w1 + (size_t)e * HID * FFNDIM;
            d = g_w1h + (size_t)e * HID * FFNDIM;
            c0 = blockIdx.x * 32; r0 = blockIdx.y * 32;
            srcC = FFNDIM; dstR = HID;
        } else {            // w2: src [FFN][HID] -> dst [HID][FFN]
            s = w2 + (size_t)e * FFNDIM * HID;
            d = g_w2h + (size_t)e * FFNDIM * HID;
            c0 = blockIdx.y * 32; r0 = blockIdx.x * 32;
            srcC = HID; dstR = FFNDIM;
        }
        #pragma unroll
        for (int i = 0; i < 32; i += 8)
            tile[ty + i][tx] = s[(size_t)(r0 + ty + i) * srcC + c0 + tx];
        __syncthreads();
        #pragma unroll
        for (int i = 0; i < 32; i += 8)
            d[(size_t)(c0 + ty + i) * dstR + r0 + tx] = __float2half_rn(tile[tx][ty + i]);
        return;
    }

    // ---- z == 0: router (+ fused fp16 convert of x) ----
    for (int i = tid; i < NE * HID; i += 256) {
        int e = i / HID, c = i - e * HID;
        srw[i] = rw[c * NE + e];
    }
    if (tid < NE) { sprob[tid] = 0.f; sgate[tid] = 0.f; }
    __syncthreads();

    const int warp = ty, lane = tx;
    const int bid = blockIdx.y * gridDim.x + blockIdx.x;
    const int t = bid * 8 + warp;
    if (t < T) {
        float p[NE];
        #pragma unroll
        for (int e = 0; e < NE; e++) p[e] = 0.f;
        const float* xr = x + (size_t)t * HID;
        __half* xhr = g_xh + (size_t)t * HID;
        for (int c = lane; c < HID; c += 32) {
            float xv = xr[c];
            xhr[c] = __float2half_rn(xv);        // fused fp16 convert
            #pragma unroll
            for (int e = 0; e < NE; e++) p[e] += xv * srw[e * HID + c];
        }
        #pragma unroll
        for (int e = 0; e < NE; e++) {
            #pragma unroll
            for (int o = 16; o > 0; o >>= 1)
                p[e] += __shfl_xor_sync(0xffffffffu, p[e], o);
        }
        if (lane == 0) {
            float lg[NE];
            #pragma unroll
            for (int e = 0; e < NE; e++) lg[e] = p[e] + rb[e];
            float m = lg[0];
            #pragma unroll
            for (int e = 1; e < NE; e++) m = fmaxf(m, lg[e]);
            float s = 0.f, pr[NE];
            #pragma unroll
            for (int e = 0; e < NE; e++) { pr[e] = expf(lg[e] - m); s += pr[e]; }
            float inv = 1.f / s;
            #pragma unroll
            for (int e = 0; e < NE; e++) {
                pr[e] *= inv;
                out_logits[(size_t)t * NE + e] = lg[e];
                out_rw[(size_t)t * NE + e] = pr[e];
                atomicAdd(&sprob[e], pr[e]);
            }
            int i1 = 0; float v1 = lg[0];
            #pragma unroll
            for (int e = 1; e < NE; e++) if (lg[e] > v1) { v1 = lg[e]; i1 = e; }
            int i2 = -1; float v2 = -3.4e38f;
            #pragma unroll
            for (int e = 0; e < NE; e++)
                if (e != i1 && lg[e] > v2) { v2 = lg[e]; i2 = e; }
            float texp = expf(v2 - v1);
            float gden = 1.f / (1.f + texp);
            float gg1 = gden, gg2 = texp * gden;
            #pragma unroll
            for (int e = 0; e < NE; e++) {
                float mv = (e == i1) ? gg1 : ((e == i2) ? gg2 : 0.f);
                out_mask[(size_t)t * NE + e] = mv;
            }
            int pos1 = atomicAdd(&g_cnt[i1], 1);
            g_list[i1 * TMAX + pos1] = t;
            g_pe[2 * t] = i1; g_ps[2 * t] = pos1; g_pgate[2 * t] = gg1;
            int pos2 = atomicAdd(&g_cnt[i2], 1);
            g_list[i2 * TMAX + pos2] = t;
            g_pe[2 * t + 1] = i2; g_ps[2 * t + 1] = pos2; g_pgate[2 * t + 1] = gg2;
            atomicAdd(&sgate[i1], gg1);
            atomicAdd(&sgate[i2], gg2);
        }
    }
    __syncthreads();
    if (tid < NE) {
        atomicAdd(&g_probsum[tid], sprob[tid]);
        atomicAdd(&g_gatesum[tid], sgate[tid]);
    }
}

__global__ void offsets_kernel(float* __restrict__ out_aux, int T) {
    if (threadIdx.x == 0 && blockIdx.x == 0) {
        int acc = 0;
        float aux = 0.f;
        #pragma unroll
        for (int e = 0; e < NE; e++) {
            g_off[e] = acc;
            acc += g_cnt[e];
            aux += g_probsum[e] * g_gatesum[e];
        }
        out_aux[0] = aux * (float)NE / ((float)T * (float)T);
    }
}

// ---------------- fp16 mma.sync grouped GEMM (round-8 winner, unchanged) ----
// CTA tile 256(M) x 128(N) x 64(K), 512 threads = 16 warps (4x4), warp tile 64x32.
// 4-stage cp.async ring, prefetch dist 2, single sync per k-tile, ldmatrix.x4.
#define BM      256
#define BN      128
#define BK      64
#define ROWH    72                    // padded row length in halves (144 B)
#define ROWB    144
#define TILEA_B (BM * ROWB)           // 36864 B
#define TILEB_B (BN * ROWB)           // 18432 B
#define STAGEB  (TILEA_B + TILEB_B)   // 55296 B
#define NSTAGE  4

template<int KDIM, int NDIM, int EPI>
__global__ void __launch_bounds__(512, 1) gemmh_kernel(const float* __restrict__ bias)
{
    const int e   = blockIdx.z;
    const int cnt = g_cnt[e];
    const int m0  = blockIdx.y * BM;
    if (m0 >= cnt) return;
    const int n0  = blockIdx.x * BN;
    const int off = g_off[e];

    extern __shared__ __half smem[];
    const uint32_t SB = (uint32_t)__cvta_generic_to_shared(smem);

    const int tid  = threadIdx.x;
    const int lane = tid & 31;
    const int wid  = tid >> 5;
    const int wm   = wid >> 2;          // 0..3
    const int wn   = wid & 3;           // 0..3
    const int gid  = lane >> 2;         // 0..7
    const int tig  = lane & 3;          // 0..3

    // ---- cp.async plumbing: 4 A rows + 2 B rows per thread ----
    const int chunk = tid & 7;          // 0..7  (16B = 8 halves)
    const int row4  = tid >> 3;         // 0..63
    const __half* asrc[4];
    const __half* bsrc[2];
    uint32_t adst[4], bdst[2];
    const __half* wT = (EPI == 1 ? g_w1h : g_w2h) + (size_t)e * KDIM * NDIM;
    #pragma unroll
    for (int i = 0; i < 4; i++) {
        int row = row4 + 64 * i;        // 0..255
        int slot = m0 + row;
        if (slot > cnt - 1) slot = cnt - 1;
        if (EPI == 1) {
            int tok = g_list[e * TMAX + slot];
            asrc[i] = g_xh + (size_t)tok * KDIM + chunk * 8;
        } else {
            asrc[i] = g_Hh + (size_t)(off + slot) * KDIM + chunk * 8;
        }
        adst[i] = SB + (uint32_t)(row * ROWB + chunk * 16);
    }
    #pragma unroll
    for (int i = 0; i < 2; i++) {
        int row = row4 + 64 * i;        // 0..127
        bsrc[i] = wT + (size_t)(n0 + row) * KDIM + chunk * 8;
        bdst[i] = SB + TILEA_B + (uint32_t)(row * ROWB + chunk * 16);
    }

    auto load_stage = [&](int s, int k0) {
        uint32_t so = (uint32_t)s * STAGEB;
        #pragma unroll
        for (int i = 0; i < 4; i++) cp16(adst[i] + so, asrc[i] + k0);
        #pragma unroll
        for (int i = 0; i < 2; i++) cp16(bdst[i] + so, bsrc[i] + k0);
    };

    float acc[4][4][4];
    #pragma unroll
    for (int mi = 0; mi < 4; mi++)
        #pragma unroll
        for (int ni = 0; ni < 4; ni++)
            #pragma unroll
            for (int r = 0; r < 4; r++) acc[mi][ni][r] = 0.f;

    constexpr int NKT = KDIM / BK;
    load_stage(0, 0);
    asm volatile("cp.async.commit_group;" ::: "memory");
    load_stage(1, BK);
    asm volatile("cp.async.commit_group;" ::: "memory");

    const int mbase = wm * 64;
    const int nbase = wn * 32;

    // ---- per-lane ldmatrix byte offsets (round-8 verified maps) ----
    const int lgrp = lane >> 3, lr = lane & 7;
    const uint32_t a_lane = (uint32_t)((((lgrp & 1) * 8 + lr) * ROWH + (lgrp >> 1) * 8) * 2);
    const uint32_t b_lane = (uint32_t)((((lgrp >> 1) * 8 + lr) * ROWH + (lgrp & 1) * 8) * 2);

    for (int kt = 0; kt < NKT; kt++) {
        if (kt + 2 < NKT) load_stage((kt + 2) & 3, (kt + 2) * BK);
        asm volatile("cp.async.commit_group;" ::: "memory");
        asm volatile("cp.async.wait_group 2;" ::: "memory");
        __syncthreads();

        const uint32_t stage = SB + (uint32_t)(kt & 3) * STAGEB;
        const uint32_t asb = stage + (uint32_t)(mbase * ROWB) + a_lane;
        const uint32_t bsb = stage + TILEA_B + (uint32_t)(nbase * ROWB) + b_lane;
        #pragma unroll
        for (int kk = 0; kk < BK; kk += 16) {
            uint32_t a[4][4], b[4][2];
            #pragma unroll
            for (int mi = 0; mi < 4; mi++)
                LDSM4(a[mi][0], a[mi][1], a[mi][2], a[mi][3],
                      asb + (uint32_t)(mi * 16 * ROWB + kk * 2));
            #pragma unroll
            for (int p = 0; p < 2; p++)
                LDSM4(b[2 * p][0], b[2 * p][1], b[2 * p + 1][0], b[2 * p + 1][1],
                      bsb + (uint32_t)(p * 16 * ROWB + kk * 2));
            #pragma unroll
            for (int mi = 0; mi < 4; mi++)
                #pragma unroll
                for (int ni = 0; ni < 4; ni++)
                    MMA16816(acc[mi][ni], a[mi], b[ni]);
        }
    }

    // ---- epilogue ----
    #pragma unroll
    for (int ni = 0; ni < 4; ni++) {
        int cc = n0 + wn * 32 + ni * 8 + 2 * tig;
        float bv0 = bias[e * NDIM + cc];
        float bv1 = bias[e * NDIM + cc + 1];
        #pragma unroll
        for (int mi = 0; mi < 4; mi++) {
            int r = m0 + wm * 64 + mi * 16 + gid;
            #pragma unroll
            for (int h = 0; h < 2; h++) {
                int rr = r + h * 8;
                if (rr < cnt) {
                    float v0 = acc[mi][ni][2 * h]     + bv0;
                    float v1 = acc[mi][ni][2 * h + 1] + bv1;
                    if (EPI == 1) {
                        __half2 hv = __floats2half2_rn(gelu_tanh(v0), gelu_tanh(v1));
                        *reinterpret_cast<__half2*>(
                            &g_Hh[(size_t)(off + rr) * NDIM + cc]) = hv;
                    } else {
                        float2 st; st.x = v0; st.y = v1;
                        *reinterpret_cast<float2*>(
                            &g_Y[(size_t)(off + rr) * NDIM + cc]) = st;
                    }
                }
            }
        }
    }
}

__global__ void combine_kernel(float* __restrict__ out, int T) {
    int total = T * (HID / 4);
    for (int i = blockIdx.x * blockDim.x + threadIdx.x; i < total;
         i += gridDim.x * blockDim.x) {
        int t = i / (HID / 4);
        int c = i - t * (HID / 4);
        int p0 = g_off[g_pe[2 * t]]     + g_ps[2 * t];
        int p1 = g_off[g_pe[2 * t + 1]] + g_ps[2 * t + 1];
        float gg0 = g_pgate[2 * t], gg1 = g_pgate[2 * t + 1];
        const float4 a = *reinterpret_cast<const float4*>(&g_Y[(size_t)p0 * HID + 4 * c]);
        const float4 b = *reinterpret_cast<const float4*>(&g_Y[(size_t)p1 * HID + 4 * c]);
        float4 o;
        o.x = gg0 * a.x + gg1 * b.x;
        o.y = gg0 * a.y + gg1 * b.y;
        o.z = gg0 * a.z + gg1 * b.z;
        o.w = gg0 * a.w + gg1 * b.w;
        reinterpret_cast<float4*>(out)[i] = o;
    }
}

// ---------------- launch ----------------
extern "C" void kernel_launch(void* const* d_in, const int* in_sizes, int n_in,
                              void* d_out, int out_size)
{
    const float* x  = (const float*)d_in[0];
    const float* rw = (const float*)d_in[1];
    const float* rb = (const float*)d_in[2];
    const float* w1 = (const float*)d_in[3];
    const float* b1 = (const float*)d_in[4];
    const float* w2 = (const float*)d_in[5];
    const float* b2 = (const float*)d_in[6];
    int T = in_sizes[0] / HID;
    if (T > TMAX) T = TMAX;

    float* out        = (float*)d_out;
    float* out_comb   = out;
    float* out_rw     = out + (size_t)T * HID;
    float* out_mask   = out_rw + (size_t)T * NE;
    float* out_aux    = out_mask + (size_t)T * NE;
    float* out_logits = out_aux + 1;

    const int smem = NSTAGE * STAGEB;   // 221184 B
    cudaFuncSetAttribute(gemmh_kernel<HID, FFNDIM, 1>,
                         cudaFuncAttributeMaxDynamicSharedMemorySize, smem);
    cudaFuncSetAttribute(gemmh_kernel<FFNDIM, HID, 2>,
                         cudaFuncAttributeMaxDynamicSharedMemorySize, smem);

    // order keeps gemm1 at launch slot #4 for the fixed-slot ncu capture
    init_kernel<<<1, 32>>>();
    front_kernel<<<dim3(96, 24, 17), dim3(32, 8)>>>(
        x, w1, w2, rw, rb, out_rw, out_mask, out_logits, T);
    offsets_kernel<<<1, 32>>>(out_aux, T);

    int mt = (T + BM - 1) / BM;
    gemmh_kernel<HID, FFNDIM, 1><<<dim3(FFNDIM / BN, mt, NE), 512, smem>>>(b1);
    gemmh_kernel<FFNDIM, HID, 2><<<dim3(HID / BN, mt, NE), 512, smem>>>(b2);

    combine_kernel<<<4096, 256>>>(out_comb, T);
}

// round 16
// speedup vs baseline: 1.0535x; 1.0042x over previous
#include <cuda_runtime.h>
#include <cuda_fp16.h>
#include <cstdint>
#include <math.h>

#define HID    768
#define FFNDIM 3072
#define NE     8
#define TMAX   16384

// ---------------- scratch (device globals: allocation-free) ----------------
__device__ __half g_xh [TMAX * HID];            // fp16 X
__device__ __half g_w1h[NE * FFNDIM * HID];     // w1 transposed: [E][FFN][HID] fp16
__device__ __half g_w2h[NE * HID * FFNDIM];     // w2 transposed: [E][HID][FFN] fp16
__device__ __half g_Hh [2 * TMAX * FFNDIM];     // gelu(X@w1+b1) fp16
__device__ int    g_cnt[NE];
__device__ int    g_off[NE];
__device__ int    g_list[NE * TMAX];            // expert,slot -> token
__device__ float  g_gslot[NE * TMAX];           // expert,slot -> gate
__device__ int    g_pe  [2 * TMAX];
__device__ int    g_ps  [2 * TMAX];
__device__ float  g_pgate[2 * TMAX];
__device__ float  g_probsum[NE];
__device__ float  g_gatesum[NE];

// ---------------- helpers ----------------
__device__ __forceinline__ void cp16(uint32_t dst, const void* src) {
    asm volatile("cp.async.cg.shared.global [%0], [%1], 16;" :: "r"(dst), "l"(src));
}
__device__ __forceinline__ float fast_tanh(float y) {
    float t = __expf(2.0f * fminf(fabsf(y), 15.0f));
    float r = (t - 1.0f) / (t + 1.0f);
    return copysignf(r, y);
}
__device__ __forceinline__ float gelu_tanh(float x) {
    float x3 = x * x * x;
    return 0.5f * x * (1.0f + fast_tanh(0.7978845608028654f * (x + 0.044715f * x3)));
}

#define LDSM4(r0, r1, r2, r3, addr) \
    asm volatile("ldmatrix.sync.aligned.m8n8.x4.shared.b16 {%0,%1,%2,%3}, [%4];" \
                 : "=r"(r0), "=r"(r1), "=r"(r2), "=r"(r3) : "r"(addr))

#define MMA16816(acc, a, b) \
    asm volatile( \
        "mma.sync.aligned.m16n8k16.row.col.f32.f16.f16.f32 " \
        "{%0,%1,%2,%3}, {%4,%5,%6,%7}, {%8,%9}, {%0,%1,%2,%3};\n" \
        : "+f"((acc)[0]), "+f"((acc)[1]), "+f"((acc)[2]), "+f"((acc)[3]) \
        : "r"((a)[0]), "r"((a)[1]), "r"((a)[2]), "r"((a)[3]), \
          "r"((b)[0]), "r"((b)[1]))

// ---------------- init (orders before the front kernel's router atomics) ----
__global__ void init_kernel() {
    int i = threadIdx.x;
    if (i < NE) { g_cnt[i] = 0; g_probsum[i] = 0.f; g_gatesum[i] = 0.f; }
}

// ---------------- front: router (z=0 FIRST) + transposes + out-zeroing ------
// grid (96, 24, 18), block (32, 8).
//   z == 0      : router (fused x->fp16 convert, records g_gslot)
//   z in [1,9)  : transpose w1 expert z-1
//   z in [9,17) : transpose w2 expert z-9
//   z == 17     : zero the combined-output slab of d_out (before gemm2 atomics)
__global__ void __launch_bounds__(256) front_kernel(
    const float* __restrict__ x,  const float* __restrict__ w1,
    const float* __restrict__ w2, const float* __restrict__ rw,
    const float* __restrict__ rb,
    float* __restrict__ out_comb,
    float* __restrict__ out_rw, float* __restrict__ out_mask,
    float* __restrict__ out_logits, int T)
{
    __shared__ float tile[32][33];
    __shared__ float srw[NE * HID];
    __shared__ float sprob[NE];
    __shared__ float sgate[NE];

    const int tx = threadIdx.x, ty = threadIdx.y;
    const int tid = ty * 32 + tx;
    const int z = blockIdx.z;

    if (z >= 1 && z <= 16) {
        // ---- weight transposes ----
        const int zz = z - 1;
        const int e = zz & 7;
        const float* s;
        __half* d;
        int c0, r0, srcC, dstR;
        if (zz < NE) {      // w1: src [HID][FFN] -> dst [FFN][HID]
            s = w1 + (size_t)e * HID * FFNDIM;
            d = g_w1h + (size_t)e * HID * FFNDIM;
            c0 = blockIdx.x * 32; r0 = blockIdx.y * 32;
            srcC = FFNDIM; dstR = HID;
        } else {            // w2: src [FFN][HID] -> dst [HID][FFN]
            s = w2 + (size_t)e * FFNDIM * HID;
            d = g_w2h + (size_t)e * FFNDIM * HID;
            c0 = blockIdx.y * 32; r0 = blockIdx.x * 32;
            srcC = HID; dstR = FFNDIM;
        }
        #pragma unroll
        for (int i = 0; i < 32; i += 8)
            tile[ty + i][tx] = s[(size_t)(r0 + ty + i) * srcC + c0 + tx];
        __syncthreads();
        #pragma unroll
        for (int i = 0; i < 32; i += 8)
            d[(size_t)(c0 + ty + i) * dstR + r0 + tx] = __float2half_rn(tile[tx][ty + i]);
        return;
    }

    if (z == 17) {
        // ---- zero combined output (float4 grid-stride) ----
        int bid = blockIdx.y * gridDim.x + blockIdx.x;
        int n4 = T * (HID / 4);
        int nb = gridDim.x * gridDim.y;
        float4 zv = make_float4(0.f, 0.f, 0.f, 0.f);
        for (int i = bid * 256 + tid; i < n4; i += nb * 256)
            reinterpret_cast<float4*>(out_comb)[i] = zv;
        return;
    }

    // ---- z == 0: router (+ fused fp16 convert of x) ----
    for (int i = tid; i < NE * HID; i += 256) {
        int e = i / HID, c = i - e * HID;
        srw[i] = rw[c * NE + e];
    }
    if (tid < NE) { sprob[tid] = 0.f; sgate[tid] = 0.f; }
    __syncthreads();

    const int warp = ty, lane = tx;
    const int bid = blockIdx.y * gridDim.x + blockIdx.x;
    const int t = bid * 8 + warp;
    if (t < T) {
        float p[NE];
        #pragma unroll
        for (int e = 0; e < NE; e++) p[e] = 0.f;
        const float* xr = x + (size_t)t * HID;
        __half* xhr = g_xh + (size_t)t * HID;
        for (int c = lane; c < HID; c += 32) {
            float xv = xr[c];
            xhr[c] = __float2half_rn(xv);        // fused fp16 convert
            #pragma unroll
            for (int e = 0; e < NE; e++) p[e] += xv * srw[e * HID + c];
        }
        #pragma unroll
        for (int e = 0; e < NE; e++) {
            #pragma unroll
            for (int o = 16; o > 0; o >>= 1)
                p[e] += __shfl_xor_sync(0xffffffffu, p[e], o);
        }
        if (lane == 0) {
            float lg[NE];
            #pragma unroll
            for (int e = 0; e < NE; e++) lg[e] = p[e] + rb[e];
            float m = lg[0];
            #pragma unroll
            for (int e = 1; e < NE; e++) m = fmaxf(m, lg[e]);
            float s = 0.f, pr[NE];
            #pragma unroll
            for (int e = 0; e < NE; e++) { pr[e] = expf(lg[e] - m); s += pr[e]; }
            float inv = 1.f / s;
            #pragma unroll
            for (int e = 0; e < NE; e++) {
                pr[e] *= inv;
                out_logits[(size_t)t * NE + e] = lg[e];
                out_rw[(size_t)t * NE + e] = pr[e];
                atomicAdd(&sprob[e], pr[e]);
            }
            int i1 = 0; float v1 = lg[0];
            #pragma unroll
            for (int e = 1; e < NE; e++) if (lg[e] > v1) { v1 = lg[e]; i1 = e; }
            int i2 = -1; float v2 = -3.4e38f;
            #pragma unroll
            for (int e = 0; e < NE; e++)
                if (e != i1 && lg[e] > v2) { v2 = lg[e]; i2 = e; }
            float texp = expf(v2 - v1);
            float gden = 1.f / (1.f + texp);
            float gg1 = gden, gg2 = texp * gden;
            #pragma unroll
            for (int e = 0; e < NE; e++) {
                float mv = (e == i1) ? gg1 : ((e == i2) ? gg2 : 0.f);
                out_mask[(size_t)t * NE + e] = mv;
            }
            int pos1 = atomicAdd(&g_cnt[i1], 1);
            g_list[i1 * TMAX + pos1] = t;
            g_gslot[i1 * TMAX + pos1] = gg1;
            g_pe[2 * t] = i1; g_ps[2 * t] = pos1; g_pgate[2 * t] = gg1;
            int pos2 = atomicAdd(&g_cnt[i2], 1);
            g_list[i2 * TMAX + pos2] = t;
            g_gslot[i2 * TMAX + pos2] = gg2;
            g_pe[2 * t + 1] = i2; g_ps[2 * t + 1] = pos2; g_pgate[2 * t + 1] = gg2;
            atomicAdd(&sgate[i1], gg1);
            atomicAdd(&sgate[i2], gg2);
        }
    }
    __syncthreads();
    if (tid < NE) {
        atomicAdd(&g_probsum[tid], sprob[tid]);
        atomicAdd(&g_gatesum[tid], sgate[tid]);
    }
}

__global__ void offsets_kernel(float* __restrict__ out_aux, int T) {
    if (threadIdx.x == 0 && blockIdx.x == 0) {
        int acc = 0;
        float aux = 0.f;
        #pragma unroll
        for (int e = 0; e < NE; e++) {
            g_off[e] = acc;
            acc += g_cnt[e];
            aux += g_probsum[e] * g_gatesum[e];
        }
        out_aux[0] = aux * (float)NE / ((float)T * (float)T);
    }
}

// ---------------- fp16 mma.sync grouped GEMM (round-8 winner core) ----------
// CTA tile 256(M) x 128(N) x 64(K), 512 threads = 16 warps (4x4), warp tile 64x32.
// 4-stage cp.async ring, prefetch dist 2, single sync per k-tile, ldmatrix.x4.
// EPI=1: out = fp16(gelu(.+b1)) -> g_Hh
// EPI=2: FUSED COMBINE: atomicAdd(out[tok] , gate * (.+b2)) — no g_Y, no combine pass
#define BM      256
#define BN      128
#define BK      64
#define ROWH    72                    // padded row length in halves (144 B)
#define ROWB    144
#define TILEA_B (BM * ROWB)           // 36864 B
#define TILEB_B (BN * ROWB)           // 18432 B
#define STAGEB  (TILEA_B + TILEB_B)   // 55296 B
#define NSTAGE  4

template<int KDIM, int NDIM, int EPI>
__global__ void __launch_bounds__(512, 1) gemmh_kernel(const float* __restrict__ bias,
                                                       float* __restrict__ outp)
{
    const int e   = blockIdx.z;
    const int cnt = g_cnt[e];
    const int m0  = blockIdx.y * BM;
    if (m0 >= cnt) return;
    const int n0  = blockIdx.x * BN;
    const int off = g_off[e];

    extern __shared__ __half smem[];
    const uint32_t SB = (uint32_t)__cvta_generic_to_shared(smem);

    const int tid  = threadIdx.x;
    const int lane = tid & 31;
    const int wid  = tid >> 5;
    const int wm   = wid >> 2;          // 0..3
    const int wn   = wid & 3;           // 0..3
    const int gid  = lane >> 2;         // 0..7
    const int tig  = lane & 3;          // 0..3

    // ---- cp.async plumbing: 4 A rows + 2 B rows per thread ----
    const int chunk = tid & 7;          // 0..7  (16B = 8 halves)
    const int row4  = tid >> 3;         // 0..63
    const __half* asrc[4];
    const __half* bsrc[2];
    uint32_t adst[4], bdst[2];
    const __half* wT = (EPI == 1 ? g_w1h : g_w2h) + (size_t)e * KDIM * NDIM;
    #pragma unroll
    for (int i = 0; i < 4; i++) {
        int row = row4 + 64 * i;        // 0..255
        int slot = m0 + row;
        if (slot > cnt - 1) slot = cnt - 1;
        if (EPI == 1) {
            int tok = g_list[e * TMAX + slot];
            asrc[i] = g_xh + (size_t)tok * KDIM + chunk * 8;
        } else {
            asrc[i] = g_Hh + (size_t)(off + slot) * KDIM + chunk * 8;
        }
        adst[i] = SB + (uint32_t)(row * ROWB + chunk * 16);
    }
    #pragma unroll
    for (int i = 0; i < 2; i++) {
        int row = row4 + 64 * i;        // 0..127
        bsrc[i] = wT + (size_t)(n0 + row) * KDIM + chunk * 8;
        bdst[i] = SB + TILEA_B + (uint32_t)(row * ROWB + chunk * 16);
    }

    auto load_stage = [&](int s, int k0) {
        uint32_t so = (uint32_t)s * STAGEB;
        #pragma unroll
        for (int i = 0; i < 4; i++) cp16(adst[i] + so, asrc[i] + k0);
        #pragma unroll
        for (int i = 0; i < 2; i++) cp16(bdst[i] + so, bsrc[i] + k0);
    };

    float acc[4][4][4];
    #pragma unroll
    for (int mi = 0; mi < 4; mi++)
        #pragma unroll
        for (int ni = 0; ni < 4; ni++)
            #pragma unroll
            for (int r = 0; r < 4; r++) acc[mi][ni][r] = 0.f;

    constexpr int NKT = KDIM / BK;
    load_stage(0, 0);
    asm volatile("cp.async.commit_group;" ::: "memory");
    load_stage(1, BK);
    asm volatile("cp.async.commit_group;" ::: "memory");

    const int mbase = wm * 64;
    const int nbase = wn * 32;

    // ---- per-lane ldmatrix byte offsets (round-8 verified maps) ----
    const int lgrp = lane >> 3, lr = lane & 7;
    const uint32_t a_lane = (uint32_t)((((lgrp & 1) * 8 + lr) * ROWH + (lgrp >> 1) * 8) * 2);
    const uint32_t b_lane = (uint32_t)((((lgrp >> 1) * 8 + lr) * ROWH + (lgrp & 1) * 8) * 2);

    for (int kt = 0; kt < NKT; kt++) {
        if (kt + 2 < NKT) load_stage((kt + 2) & 3, (kt + 2) * BK);
        asm volatile("cp.async.commit_group;" ::: "memory");
        asm volatile("cp.async.wait_group 2;" ::: "memory");
        __syncthreads();

        const uint32_t stage = SB + (uint32_t)(kt & 3) * STAGEB;
        const uint32_t asb = stage + (uint32_t)(mbase * ROWB) + a_lane;
        const uint32_t bsb = stage + TILEA_B + (uint32_t)(nbase * ROWB) + b_lane;
        #pragma unroll
        for (int kk = 0; kk < BK; kk += 16) {
            uint32_t a[4][4], b[4][2];
            #pragma unroll
            for (int mi = 0; mi < 4; mi++)
                LDSM4(a[mi][0], a[mi][1], a[mi][2], a[mi][3],
                      asb + (uint32_t)(mi * 16 * ROWB + kk * 2));
            #pragma unroll
            for (int p = 0; p < 2; p++)
                LDSM4(b[2 * p][0], b[2 * p][1], b[2 * p + 1][0], b[2 * p + 1][1],
                      bsb + (uint32_t)(p * 16 * ROWB + kk * 2));
            #pragma unroll
            for (int mi = 0; mi < 4; mi++)
                #pragma unroll
                for (int ni = 0; ni < 4; ni++)
                    MMA16816(acc[mi][ni], a[mi], b[ni]);
        }
    }

    // ---- epilogue ----
    int   toks [4][2];
    float gates[4][2];
    if (EPI == 2) {
        #pragma unroll
        for (int mi = 0; mi < 4; mi++) {
            int r = m0 + wm * 64 + mi * 16 + gid;
            #pragma unroll
            for (int h = 0; h < 2; h++) {
                int rr = r + h * 8;
                if (rr < cnt) {
                    toks [mi][h] = g_list [e * TMAX + rr];
                    gates[mi][h] = g_gslot[e * TMAX + rr];
                } else { toks[mi][h] = 0; gates[mi][h] = 0.f; }
            }
        }
    }
    #pragma unroll
    for (int ni = 0; ni < 4; ni++) {
        int cc = n0 + wn * 32 + ni * 8 + 2 * tig;
        float bv0 = bias[e * NDIM + cc];
        float bv1 = bias[e * NDIM + cc + 1];
        #pragma unroll
        for (int mi = 0; mi < 4; mi++) {
            int r = m0 + wm * 64 + mi * 16 + gid;
            #pragma unroll
            for (int h = 0; h < 2; h++) {
                int rr = r + h * 8;
                if (rr < cnt) {
                    float v0 = acc[mi][ni][2 * h]     + bv0;
                    float v1 = acc[mi][ni][2 * h + 1] + bv1;
                    if (EPI == 1) {
                        __half2 hv = __floats2half2_rn(gelu_tanh(v0), gelu_tanh(v1));
                        *reinterpret_cast<__half2*>(
                            &g_Hh[(size_t)(off + rr) * NDIM + cc]) = hv;
                    } else {
                        float g = gates[mi][h];
                        float* orow = outp + (size_t)toks[mi][h] * NDIM + cc;
                        atomicAdd(orow,     g * v0);
                        atomicAdd(orow + 1, g * v1);
                    }
                }
            }
        }
    }
}

// ---------------- launch ----------------
extern "C" void kernel_launch(void* const* d_in, const int* in_sizes, int n_in,
                              void* d_out, int out_size)
{
    const float* x  = (const float*)d_in[0];
    const float* rw = (const float*)d_in[1];
    const float* rb = (const float*)d_in[2];
    const float* w1 = (const float*)d_in[3];
    const float* b1 = (const float*)d_in[4];
    const float* w2 = (const float*)d_in[5];
    const float* b2 = (const float*)d_in[6];
    int T = in_sizes[0] / HID;
    if (T > TMAX) T = TMAX;

    float* out        = (float*)d_out;
    float* out_comb   = out;
    float* out_rw     = out + (size_t)T * HID;
    float* out_mask   = out_rw + (size_t)T * NE;
    float* out_aux    = out_mask + (size_t)T * NE;
    float* out_logits = out_aux + 1;

    const int smem = NSTAGE * STAGEB;   // 221184 B
    cudaFuncSetAttribute(gemmh_kernel<HID, FFNDIM, 1>,
                         cudaFuncAttributeMaxDynamicSharedMemorySize, smem);
    cudaFuncSetAttribute(gemmh_kernel<FFNDIM, HID, 2>,
                         cudaFuncAttributeMaxDynamicSharedMemorySize, smem);

    // order keeps gemm1 at launch slot #4 for the fixed-slot ncu capture
    init_kernel<<<1, 32>>>();
    front_kernel<<<dim3(96, 24, 18), dim3(32, 8)>>>(
        x, w1, w2, rw, rb, out_comb, out_rw, out_mask, out_logits, T);
    offsets_kernel<<<1, 32>>>(out_aux, T);

    int mt = (T + BM - 1) / BM;
    gemmh_kernel<HID, FFNDIM, 1><<<dim3(FFNDIM / BN, mt, NE), 512, smem>>>(b1, nullptr);
    gemmh_kernel<FFNDIM, HID, 2><<<dim3(HID / BN, mt, NE), 512, smem>>>(b2, out_comb);
}